// round 12
// baseline (speedup 1.0000x reference)
#include <cuda_runtime.h>
#include <cuda_fp16.h>
#include <math.h>
#include <stdint.h>

// Problem constants
#define B_  2
#define T_  2048
#define D_  2048
#define H_  16
#define DH_ 128
#define M_  4096            // B_*T_

// ---------------- scratch (__device__ globals; no allocs allowed) ----------
__device__ __align__(256) float g_q[8388608];
__device__ __align__(256) float g_k[8388608];
__device__ __align__(256) __half g_xh[8388608], g_xl[8388608];
__device__ __align__(256) __half g_qh[8388608], g_ql[8388608];
__device__ __align__(256) __half g_k16[8388608];
__device__ __align__(256) __half g_v16[8388608];
__device__ __align__(256) __half g_oh[8388608], g_ol[8388608];
__device__ __align__(256) __half g_wq16[4194304], g_wk16[4194304];
__device__ __align__(256) __half g_wv16[4194304], g_wo16[4194304];

// ---------------- PTX helpers ----------------------------------------------
__device__ __forceinline__ uint32_t smem_u32(const void* p) {
    uint32_t a;
    asm("{ .reg .u64 t; cvta.to.shared.u64 t, %1; cvt.u32.u64 %0, t; }" : "=r"(a) : "l"(p));
    return a;
}
__device__ __forceinline__ void cpa16(uint32_t s, const void* g) {
    asm volatile("cp.async.cg.shared.global [%0], [%1], 16;" :: "r"(s), "l"(g));
}
__device__ __forceinline__ void ldx4(uint32_t* d, uint32_t addr) {
    asm volatile("ldmatrix.sync.aligned.m8n8.x4.shared.b16 {%0,%1,%2,%3}, [%4];"
                 : "=r"(d[0]), "=r"(d[1]), "=r"(d[2]), "=r"(d[3]) : "r"(addr));
}
__device__ __forceinline__ void ldx2(uint32_t* d, uint32_t addr) {
    asm volatile("ldmatrix.sync.aligned.m8n8.x2.shared.b16 {%0,%1}, [%2];"
                 : "=r"(d[0]), "=r"(d[1]) : "r"(addr));
}
__device__ __forceinline__ void ldx2t(uint32_t* d, uint32_t addr) {
    asm volatile("ldmatrix.sync.aligned.m8n8.x2.trans.shared.b16 {%0,%1}, [%2];"
                 : "=r"(d[0]), "=r"(d[1]) : "r"(addr));
}
__device__ __forceinline__ void mma_f16(float* c, const uint32_t* a, const uint32_t* b) {
    asm volatile(
        "mma.sync.aligned.m16n8k16.row.col.f32.f16.f16.f32 "
        "{%0,%1,%2,%3}, {%4,%5,%6,%7}, {%8,%9}, {%0,%1,%2,%3};"
        : "+f"(c[0]), "+f"(c[1]), "+f"(c[2]), "+f"(c[3])
        : "r"(a[0]), "r"(a[1]), "r"(a[2]), "r"(a[3]), "r"(b[0]), "r"(b[1]));
}
__device__ __forceinline__ uint32_t pkh(__half a, __half b) {
    __half2 t = __halves2half2(a, b);
    return *(uint32_t*)&t;
}
__device__ __forceinline__ __half2 split_h2(float a, float b, __half2& lo) {
    __half h0 = __float2half_rn(a), h1 = __float2half_rn(b);
    lo = __halves2half2(__float2half_rn(a - __half2float(h0)),
                        __float2half_rn(b - __half2float(h1)));
    return __halves2half2(h0, h1);
}
// swizzle for 64-byte rows
__device__ __forceinline__ uint32_t swz(uint32_t off) { return off ^ ((off >> 3) & 0x30); }

// ---------------------------------------------------------------------------
// fp16 2-pass GEMM-NT: C[m][n] = sum_k (Ah+Al)[m][k]*Bf[n][k] + bias[n]
// BM=128, BN=256, BK=32. 256 threads = 8 warps (2m x 4n), warp tile 64x64.
// 3 smem stages x 32KB (Ah 8K | Al 8K | B 16K).
// Inner loop: full hi-sweep then full lo-sweep (acc reuse distance 32 mmas,
// avoids adjacent RAW on HMMA accumulators).
// ---------------------------------------------------------------------------
#define GSTAGE 32768
#define GEMM_SMEM (3 * GSTAGE)

__global__ __launch_bounds__(256, 1) void gemm_f16_2p(
    const __half* __restrict__ Ah, const __half* __restrict__ Al,
    const __half* __restrict__ Bf,
    const float* __restrict__ bias, float* __restrict__ C,
    __half* __restrict__ OutF,
    int Md, int Nd, int Kd)
{
    extern __shared__ __align__(1024) unsigned char smem[];
    const int tid = threadIdx.x;
    const int wid = tid >> 5;
    const int lane = tid & 31;
    const int wm = wid >> 2;              // 0..1
    const int wn = wid & 3;               // 0..3
    const int bm = blockIdx.y * 128;
    const int bn = blockIdx.x * 256;
    const uint32_t sbase = smem_u32(smem);
    const int nchunk = Kd >> 5;           // 64

#define LOAD_STAGE(stage, k0)                                                   \
    {                                                                            \
        uint32_t sb = sbase + (stage) * GSTAGE;                                  \
        _Pragma("unroll")                                                        \
        for (int j = 0; j < 2; j++) {                                            \
            int idx = tid + j * 256;                                             \
            int r = idx >> 2, c = idx & 3;                                       \
            uint32_t so = swz((uint32_t)(r * 64 + c * 16));                      \
            size_t ga = (size_t)(bm + r) * Kd + (k0) + c * 8;                    \
            cpa16(sb + so,        Ah + ga);                                      \
            cpa16(sb + 8192 + so, Al + ga);                                      \
        }                                                                        \
        _Pragma("unroll")                                                        \
        for (int j = 0; j < 4; j++) {                                            \
            int idx = tid + j * 256;                                             \
            int r = idx >> 2, c = idx & 3;                                       \
            uint32_t so = swz((uint32_t)(r * 64 + c * 16));                      \
            size_t gb = (size_t)(bn + r) * Kd + (k0) + c * 8;                    \
            cpa16(sb + 16384 + so, Bf + gb);                                     \
        }                                                                        \
        asm volatile("cp.async.commit_group;" ::: "memory");                     \
    }

    LOAD_STAGE(0, 0)
    LOAD_STAGE(1, 32)

    float acc[4][8][4];
#pragma unroll
    for (int i = 0; i < 4; i++)
#pragma unroll
        for (int j = 0; j < 8; j++)
#pragma unroll
            for (int l = 0; l < 4; l++) acc[i][j][l] = 0.f;

    const int arow = lane & 15;
    const int akh = lane >> 4;
    const int brow8 = lane & 7;
    const int bkh = (lane >> 3) & 1;
    const int bni8 = (lane >> 4) & 1;

    for (int i = 0; i < nchunk; i++) {
        if (i + 2 < nchunk) {
            LOAD_STAGE((i + 2) % 3, (i + 2) * 32)
            asm volatile("cp.async.wait_group 2;" ::: "memory");
        } else if (i + 1 < nchunk) {
            asm volatile("cp.async.wait_group 1;" ::: "memory");
        } else {
            asm volatile("cp.async.wait_group 0;" ::: "memory");
        }
        __syncthreads();

        const uint32_t sb = sbase + (i % 3) * GSTAGE;
#pragma unroll
        for (int ks = 0; ks < 2; ks++) {
            uint32_t ah[4][4], al[4][4], bf[4][4];
#pragma unroll
            for (int mi = 0; mi < 4; mi++) {
                uint32_t off = swz((uint32_t)((wm * 64 + mi * 16 + arow) * 64 + ks * 32 + akh * 16));
                ldx4(ah[mi], sb + off);
                ldx4(al[mi], sb + 8192 + off);
            }
#pragma unroll
            for (int nj = 0; nj < 4; nj++) {
                int r = wn * 64 + nj * 16 + bni8 * 8 + brow8;
                uint32_t off = swz((uint32_t)(r * 64 + ks * 32 + bkh * 16));
                ldx4(bf[nj], sb + 16384 + off);
            }
            // hi sweep: 32 independent mmas
#pragma unroll
            for (int mi = 0; mi < 4; mi++)
#pragma unroll
                for (int nj = 0; nj < 4; nj++) {
                    mma_f16(acc[mi][2 * nj],     ah[mi], &bf[nj][0]);
                    mma_f16(acc[mi][2 * nj + 1], ah[mi], &bf[nj][2]);
                }
            // lo sweep: acc reuse distance = 32 mmas
#pragma unroll
            for (int mi = 0; mi < 4; mi++)
#pragma unroll
                for (int nj = 0; nj < 4; nj++) {
                    mma_f16(acc[mi][2 * nj],     al[mi], &bf[nj][0]);
                    mma_f16(acc[mi][2 * nj + 1], al[mi], &bf[nj][2]);
                }
        }
        __syncthreads();
    }

    // Epilogue
#pragma unroll
    for (int mi = 0; mi < 4; mi++) {
        int r0 = bm + wm * 64 + mi * 16 + (lane >> 2);
#pragma unroll
        for (int ni = 0; ni < 8; ni++) {
            int col = bn + wn * 64 + ni * 8 + (lane & 3) * 2;
            float b0 = bias[col], b1 = bias[col + 1];
            float x0 = acc[mi][ni][0] + b0, x1 = acc[mi][ni][1] + b1;
            float x2 = acc[mi][ni][2] + b0, x3 = acc[mi][ni][3] + b1;
            if (C) {
                *(float2*)(C + (size_t)r0 * Nd + col) = make_float2(x0, x1);
                *(float2*)(C + (size_t)(r0 + 8) * Nd + col) = make_float2(x2, x3);
            }
            if (OutF) {
                *(__half2*)(OutF + (size_t)r0 * Nd + col) = __floats2half2_rn(x0, x1);
                *(__half2*)(OutF + (size_t)(r0 + 8) * Nd + col) = __floats2half2_rn(x2, x3);
            }
        }
    }
#undef LOAD_STAGE
}

// ---------------------------------------------------------------------------
// fp32 -> fp16 hi/lo split (lo optional)
// ---------------------------------------------------------------------------
__global__ __launch_bounds__(256) void split_f16(
    const float4* __restrict__ src, __half2* __restrict__ hi,
    __half2* __restrict__ lo, int n4)
{
    int i = blockIdx.x * 256 + threadIdx.x;
    if (i >= n4) return;
    float4 v = src[i];
    __half2 l0, l1;
    __half2 h0 = split_h2(v.x, v.y, l0);
    __half2 h1 = split_h2(v.z, v.w, l1);
    hi[2 * i] = h0; hi[2 * i + 1] = h1;
    if (lo) { lo[2 * i] = l0; lo[2 * i + 1] = l1; }
}

// ---------------------------------------------------------------------------
// Fused RMSNorm + interleaved RoPE -> fp16 hi (+ optional lo split).
// ---------------------------------------------------------------------------
__global__ __launch_bounds__(256) void rmsnorm_rope_f16(
    const float* __restrict__ h, const float* __restrict__ w,
    const float* __restrict__ cosb, const float* __restrict__ sinb,
    __half* __restrict__ outh, __half* __restrict__ outl)
{
    const int row = blockIdx.x;
    const int t = row & (T_ - 1);
    const float* hr = h + (size_t)row * D_;

    float ss = 0.f;
    for (int i = threadIdx.x; i < D_; i += 256) { float v = hr[i]; ss += v * v; }
#pragma unroll
    for (int o = 16; o > 0; o >>= 1) ss += __shfl_xor_sync(0xffffffffu, ss, o);
    __shared__ float red[8];
    __shared__ float s_inv;
    if ((threadIdx.x & 31) == 0) red[threadIdx.x >> 5] = ss;
    __syncthreads();
    if (threadIdx.x == 0) {
        float s = 0.f;
        for (int i = 0; i < 8; i++) s += red[i];
        s_inv = rsqrtf(s * (1.0f / D_) + 1e-6f);
    }
    __syncthreads();
    const float inv = s_inv;
    const float* ct = cosb + (size_t)t * D_;
    const float* st = sinb + (size_t)t * D_;
    __half2* oh2 = (__half2*)(outh + (size_t)row * D_);
    __half2* ol2 = outl ? (__half2*)(outl + (size_t)row * D_) : nullptr;
    for (int i = threadIdx.x; i < D_ / 2; i += 256) {
        int i2 = i * 2;
        float e = hr[i2] * inv * w[i2];
        float o = hr[i2 + 1] * inv * w[i2 + 1];
        float v0 = e * ct[i2]     - o * st[i2];
        float v1 = o * ct[i2 + 1] + e * st[i2 + 1];
        __half2 lo;
        __half2 hi = split_h2(v0, v1, lo);
        oh2[i] = hi;
        if (ol2) ol2[i] = lo;
    }
}

// ---------------------------------------------------------------------------
// fp16 2-pass mma.sync flash attention (non-causal); output fp16 hi/lo split.
// Q split, K single, V single (P split in-register). Dependency-aware
// mma ordering: per frag-group, hi sweep then lo sweep.
// ---------------------------------------------------------------------------
#define FA_STAGE 32768

__global__ __launch_bounds__(128, 1) void flash_attn_f16(
    const __half* __restrict__ Qh, const __half* __restrict__ Ql,
    const __half* __restrict__ Kf, const __half* __restrict__ Vf,
    __half* __restrict__ Oh, __half* __restrict__ Ol)
{
    extern __shared__ __align__(1024) unsigned char smem[];
    const int tid = threadIdx.x;
    const int wid = tid >> 5, lane = tid & 31;
    const int b = blockIdx.z, h = blockIdx.y;
    const int q0 = blockIdx.x * 64;
    const uint32_t sbase = smem_u32(smem);
    const size_t rowbase = ((size_t)b * T_) * D_ + h * DH_;

#define LOADKV(it_, stg)                                                         \
    {                                                                            \
        uint32_t sb_ = sbase + (stg) * FA_STAGE;                                 \
        size_t base_ = rowbase + (size_t)((it_) * 64) * D_;                      \
        for (int t = tid; t < 1024; t += 128) {                                  \
            int r_ = t >> 4, c_ = t & 15;                                        \
            uint32_t ph_ = r_ * 256 + ((c_ ^ (r_ & 7)) << 4);                    \
            size_t g_ = base_ + (size_t)r_ * D_ + c_ * 8;                        \
            cpa16(sb_ + ph_,          Kf + g_);                                  \
            cpa16(sb_ + 16384 + ph_,  Vf + g_);                                  \
        }                                                                        \
        asm volatile("cp.async.commit_group;" ::: "memory");                     \
    }

    // stage Q (hi at 0, lo at +16K), build fragments
    for (int t = tid; t < 1024; t += 128) {
        int r = t >> 4, c = t & 15;
        uint32_t ph = r * 256 + ((c ^ (r & 7)) << 4);
        size_t g = rowbase + (size_t)(q0 + r) * D_ + c * 8;
        cpa16(sbase + ph, Qh + g);
        cpa16(sbase + 16384 + ph, Ql + g);
    }
    asm volatile("cp.async.commit_group;" ::: "memory");
    asm volatile("cp.async.wait_group 0;" ::: "memory");
    __syncthreads();

    uint32_t qh[8][4], ql[8][4];
    {
        int r = wid * 16 + (lane & 15);
        int khalf = lane >> 4;
#pragma unroll
        for (int kk = 0; kk < 8; kk++) {
            int chunk = kk * 2 + khalf;
            uint32_t ph = r * 256 + ((chunk ^ (r & 7)) << 4);
            ldx4(qh[kk], sbase + ph);
            ldx4(ql[kk], sbase + 16384 + ph);
        }
    }
    __syncthreads();

    float o[16][4];
#pragma unroll
    for (int i = 0; i < 16; i++)
#pragma unroll
        for (int j = 0; j < 4; j++) o[i][j] = 0.f;
    float m0 = -1e30f, m1 = -1e30f, l0 = 0.f, l1 = 0.f;

    LOADKV(0, 0)
    LOADKV(1, 1)

    const float scale = 0.08838834764831845f;
    const int NIT = T_ / 64;

    for (int it = 0; it < NIT; it++) {
        if (it < NIT - 1) { asm volatile("cp.async.wait_group 1;" ::: "memory"); }
        else              { asm volatile("cp.async.wait_group 0;" ::: "memory"); }
        __syncthreads();
        const uint32_t sb = sbase + (it & 1) * FA_STAGE;

        // ---- S = (Qh+Ql) K^T : per kk, load 8 K-frags, hi sweep, lo sweep ----
        float s[8][4];
#pragma unroll
        for (int n = 0; n < 8; n++)
#pragma unroll
            for (int j = 0; j < 4; j++) s[n][j] = 0.f;

        const int krow_lo = lane & 7;
        const int kkh = ((lane & 15) >> 3) & 1;
#pragma unroll
        for (int kk = 0; kk < 8; kk++) {
            uint32_t bhv[8][2];
#pragma unroll
            for (int n = 0; n < 8; n++) {
                int r = n * 8 + krow_lo;
                int chunk = kk * 2 + kkh;
                uint32_t ph = r * 256 + ((chunk ^ (r & 7)) << 4);
                ldx2(bhv[n], sb + ph);
            }
#pragma unroll
            for (int n = 0; n < 8; n++) mma_f16(s[n], qh[kk], bhv[n]);
#pragma unroll
            for (int n = 0; n < 8; n++) mma_f16(s[n], ql[kk], bhv[n]);
        }

#pragma unroll
        for (int n = 0; n < 8; n++)
#pragma unroll
            for (int j = 0; j < 4; j++) s[n][j] *= scale;

        // ---- online softmax ----
        float cm0 = -1e30f, cm1 = -1e30f;
#pragma unroll
        for (int n = 0; n < 8; n++) {
            cm0 = fmaxf(cm0, fmaxf(s[n][0], s[n][1]));
            cm1 = fmaxf(cm1, fmaxf(s[n][2], s[n][3]));
        }
        cm0 = fmaxf(cm0, __shfl_xor_sync(0xffffffffu, cm0, 1));
        cm0 = fmaxf(cm0, __shfl_xor_sync(0xffffffffu, cm0, 2));
        cm1 = fmaxf(cm1, __shfl_xor_sync(0xffffffffu, cm1, 1));
        cm1 = fmaxf(cm1, __shfl_xor_sync(0xffffffffu, cm1, 2));
        float mn0 = fmaxf(m0, cm0), mn1 = fmaxf(m1, cm1);
        float a0 = __expf(m0 - mn0), a1 = __expf(m1 - mn1);
        float sum0 = 0.f, sum1 = 0.f;
#pragma unroll
        for (int n = 0; n < 8; n++) {
            s[n][0] = __expf(s[n][0] - mn0);
            s[n][1] = __expf(s[n][1] - mn0);
            s[n][2] = __expf(s[n][2] - mn1);
            s[n][3] = __expf(s[n][3] - mn1);
            sum0 += s[n][0] + s[n][1];
            sum1 += s[n][2] + s[n][3];
        }
        sum0 += __shfl_xor_sync(0xffffffffu, sum0, 1);
        sum0 += __shfl_xor_sync(0xffffffffu, sum0, 2);
        sum1 += __shfl_xor_sync(0xffffffffu, sum1, 1);
        sum1 += __shfl_xor_sync(0xffffffffu, sum1, 2);
        l0 = l0 * a0 + sum0;
        l1 = l1 * a1 + sum1;
        m0 = mn0; m1 = mn1;
#pragma unroll
        for (int ni = 0; ni < 16; ni++) {
            o[ni][0] *= a0; o[ni][1] *= a0;
            o[ni][2] *= a1; o[ni][3] *= a1;
        }

        // ---- O += (Ph+Pl) V : per j, two ni-blocks of 8, hi sweep then lo ----
        const int vrow = lane & 15;
#pragma unroll
        for (int j = 0; j < 4; j++) {
            uint32_t pa[4], pb[4];
#pragma unroll
            for (int half = 0; half < 2; half++) {
                float x0 = s[2 * j + half][0], x1 = s[2 * j + half][1];
                float x2 = s[2 * j + half][2], x3 = s[2 * j + half][3];
                __half h0 = __float2half_rn(x0), h1 = __float2half_rn(x1);
                __half h2 = __float2half_rn(x2), h3 = __float2half_rn(x3);
                pa[2 * half]     = pkh(h0, h1);
                pa[2 * half + 1] = pkh(h2, h3);
                pb[2 * half]     = pkh(__float2half_rn(x0 - __half2float(h0)),
                                       __float2half_rn(x1 - __half2float(h1)));
                pb[2 * half + 1] = pkh(__float2half_rn(x2 - __half2float(h2)),
                                       __float2half_rn(x3 - __half2float(h3)));
            }
            int r = j * 16 + vrow;
#pragma unroll
            for (int blk = 0; blk < 2; blk++) {
                uint32_t vhv[8][2];
#pragma unroll
                for (int nn = 0; nn < 8; nn++) {
                    int ni = blk * 8 + nn;
                    uint32_t ph = r * 256 + ((ni ^ (r & 7)) << 4);
                    ldx2t(vhv[nn], sb + 16384 + ph);
                }
#pragma unroll
                for (int nn = 0; nn < 8; nn++) mma_f16(o[blk * 8 + nn], pa, vhv[nn]);
#pragma unroll
                for (int nn = 0; nn < 8; nn++) mma_f16(o[blk * 8 + nn], pb, vhv[nn]);
            }
        }
        __syncthreads();
        if (it + 2 < NIT) { LOADKV(it + 2, it & 1) }
    }

    // ---- store as fp16 hi/lo split ----
    float i0 = 1.f / l0, i1 = 1.f / l1;
    int r_lo = q0 + wid * 16 + (lane >> 2);
#pragma unroll
    for (int ni = 0; ni < 16; ni++) {
        int col = ni * 8 + (lane & 3) * 2;
        size_t idx0 = rowbase + (size_t)r_lo * D_ + col;
        size_t idx1 = rowbase + (size_t)(r_lo + 8) * D_ + col;
        __half2 lo0, lo1;
        __half2 h0 = split_h2(o[ni][0] * i0, o[ni][1] * i0, lo0);
        __half2 h1 = split_h2(o[ni][2] * i1, o[ni][3] * i1, lo1);
        *(__half2*)(Oh + idx0) = h0;
        *(__half2*)(Ol + idx0) = lo0;
        *(__half2*)(Oh + idx1) = h1;
        *(__half2*)(Ol + idx1) = lo1;
    }
#undef LOADKV
}

// ---------------------------------------------------------------------------
// Launch
// ---------------------------------------------------------------------------
extern "C" void kernel_launch(void* const* d_in, const int* in_sizes, int n_in,
                              void* d_out, int out_size)
{
    const float* x    = (const float*)d_in[0];
    const float* cosb = (const float*)d_in[1];
    const float* sinb = (const float*)d_in[2];
    const float* Wq   = (const float*)d_in[3];
    const float* bq   = (const float*)d_in[4];
    const float* Wk   = (const float*)d_in[5];
    const float* bk   = (const float*)d_in[6];
    const float* Wv   = (const float*)d_in[7];
    const float* bv   = (const float*)d_in[8];
    const float* qnw  = (const float*)d_in[9];
    const float* knw  = (const float*)d_in[10];
    const float* Wo   = (const float*)d_in[11];
    const float* bo   = (const float*)d_in[12];
    float* out = (float*)d_out;

    float *qp, *kp;
    cudaGetSymbolAddress((void**)&qp, g_q);
    cudaGetSymbolAddress((void**)&kp, g_k);
    __half *xh, *xl, *qhp, *qlp, *k16, *v16, *ohp, *olp;
    __half *wq16, *wk16, *wv16, *wo16;
    cudaGetSymbolAddress((void**)&xh, g_xh);    cudaGetSymbolAddress((void**)&xl, g_xl);
    cudaGetSymbolAddress((void**)&qhp, g_qh);   cudaGetSymbolAddress((void**)&qlp, g_ql);
    cudaGetSymbolAddress((void**)&k16, g_k16);  cudaGetSymbolAddress((void**)&v16, g_v16);
    cudaGetSymbolAddress((void**)&ohp, g_oh);   cudaGetSymbolAddress((void**)&olp, g_ol);
    cudaGetSymbolAddress((void**)&wq16, g_wq16); cudaGetSymbolAddress((void**)&wk16, g_wk16);
    cudaGetSymbolAddress((void**)&wv16, g_wv16); cudaGetSymbolAddress((void**)&wo16, g_wo16);

    const int nx4 = M_ * D_ / 4;
    const int nw4 = D_ * D_ / 4;
    split_f16<<<nx4 / 256, 256>>>((const float4*)x,  (__half2*)xh,   (__half2*)xl, nx4);
    split_f16<<<nw4 / 256, 256>>>((const float4*)Wq, (__half2*)wq16, nullptr, nw4);
    split_f16<<<nw4 / 256, 256>>>((const float4*)Wk, (__half2*)wk16, nullptr, nw4);
    split_f16<<<nw4 / 256, 256>>>((const float4*)Wv, (__half2*)wv16, nullptr, nw4);
    split_f16<<<nw4 / 256, 256>>>((const float4*)Wo, (__half2*)wo16, nullptr, nw4);

    cudaFuncSetAttribute(gemm_f16_2p, cudaFuncAttributeMaxDynamicSharedMemorySize, GEMM_SMEM);
    dim3 ggrid(D_ / 256, M_ / 128);   // (8, 32)
    gemm_f16_2p<<<ggrid, 256, GEMM_SMEM>>>(xh, xl, wq16, bq, qp, nullptr, M_, D_, D_);
    gemm_f16_2p<<<ggrid, 256, GEMM_SMEM>>>(xh, xl, wk16, bk, kp, nullptr, M_, D_, D_);
    gemm_f16_2p<<<ggrid, 256, GEMM_SMEM>>>(xh, xl, wv16, bv, nullptr, v16, M_, D_, D_);

    rmsnorm_rope_f16<<<M_, 256>>>(qp, qnw, cosb, sinb, qhp, qlp);
    rmsnorm_rope_f16<<<M_, 256>>>(kp, knw, cosb, sinb, k16, nullptr);

    cudaFuncSetAttribute(flash_attn_f16, cudaFuncAttributeMaxDynamicSharedMemorySize, 2 * FA_STAGE);
    flash_attn_f16<<<dim3(T_ / 64, H_, B_), 128, 2 * FA_STAGE>>>(qhp, qlp, k16, v16, ohp, olp);

    gemm_f16_2p<<<ggrid, 256, GEMM_SMEM>>>(ohp, olp, wo16, bo, out, nullptr, M_, D_, D_);
}

// round 13
// speedup vs baseline: 1.2013x; 1.2013x over previous
#include <cuda_runtime.h>
#include <cuda_fp16.h>
#include <math.h>
#include <stdint.h>

// Problem constants
#define B_  2
#define T_  2048
#define D_  2048
#define H_  16
#define DH_ 128
#define M_  4096            // B_*T_

// ---------------- scratch (__device__ globals; no allocs allowed) ----------
__device__ __align__(256) float g_q[8388608];
__device__ __align__(256) float g_k[8388608];
__device__ __align__(256) __half g_xh[8388608];
__device__ __align__(256) __half g_qh[8388608], g_ql[8388608];
__device__ __align__(256) __half g_k16[8388608];
__device__ __align__(256) __half g_v16[8388608];
__device__ __align__(256) __half g_oh[8388608], g_ol[8388608];
__device__ __align__(256) __half g_wq16[4194304], g_wk16[4194304];
__device__ __align__(256) __half g_wv16[4194304], g_wo16[4194304];

// ---------------- PTX helpers ----------------------------------------------
__device__ __forceinline__ uint32_t smem_u32(const void* p) {
    uint32_t a;
    asm("{ .reg .u64 t; cvta.to.shared.u64 t, %1; cvt.u32.u64 %0, t; }" : "=r"(a) : "l"(p));
    return a;
}
__device__ __forceinline__ void cpa16(uint32_t s, const void* g) {
    asm volatile("cp.async.cg.shared.global [%0], [%1], 16;" :: "r"(s), "l"(g));
}
__device__ __forceinline__ void ldx4(uint32_t* d, uint32_t addr) {
    asm volatile("ldmatrix.sync.aligned.m8n8.x4.shared.b16 {%0,%1,%2,%3}, [%4];"
                 : "=r"(d[0]), "=r"(d[1]), "=r"(d[2]), "=r"(d[3]) : "r"(addr));
}
__device__ __forceinline__ void ldx2(uint32_t* d, uint32_t addr) {
    asm volatile("ldmatrix.sync.aligned.m8n8.x2.shared.b16 {%0,%1}, [%2];"
                 : "=r"(d[0]), "=r"(d[1]) : "r"(addr));
}
__device__ __forceinline__ void ldx2t(uint32_t* d, uint32_t addr) {
    asm volatile("ldmatrix.sync.aligned.m8n8.x2.trans.shared.b16 {%0,%1}, [%2];"
                 : "=r"(d[0]), "=r"(d[1]) : "r"(addr));
}
__device__ __forceinline__ void mma_f16(float* c, const uint32_t* a, const uint32_t* b) {
    asm volatile(
        "mma.sync.aligned.m16n8k16.row.col.f32.f16.f16.f32 "
        "{%0,%1,%2,%3}, {%4,%5,%6,%7}, {%8,%9}, {%0,%1,%2,%3};"
        : "+f"(c[0]), "+f"(c[1]), "+f"(c[2]), "+f"(c[3])
        : "r"(a[0]), "r"(a[1]), "r"(a[2]), "r"(a[3]), "r"(b[0]), "r"(b[1]));
}
__device__ __forceinline__ uint32_t pkh(__half a, __half b) {
    __half2 t = __halves2half2(a, b);
    return *(uint32_t*)&t;
}
__device__ __forceinline__ __half2 split_h2(float a, float b, __half2& lo) {
    __half h0 = __float2half_rn(a), h1 = __float2half_rn(b);
    lo = __halves2half2(__float2half_rn(a - __half2float(h0)),
                        __float2half_rn(b - __half2float(h1)));
    return __halves2half2(h0, h1);
}
// swizzle for 64-byte rows
__device__ __forceinline__ uint32_t swz(uint32_t off) { return off ^ ((off >> 3) & 0x30); }

// ---------------------------------------------------------------------------
// fp16 GEMM-NT: C[m][n] = sum_k (Ah[+Al])[m][k]*Bf[n][k] + bias[n]
// Al == nullptr -> single-pass. BM=128, BN=256, BK=32. 256 threads = 8 warps
// (2m x 4n), warp tile 64x64. 3 smem stages x 32KB (Ah 8K | Al 8K | B 16K).
// ---------------------------------------------------------------------------
#define GSTAGE 32768
#define GEMM_SMEM (3 * GSTAGE)

__global__ __launch_bounds__(256, 1) void gemm_f16_2p(
    const __half* __restrict__ Ah, const __half* __restrict__ Al,
    const __half* __restrict__ Bf,
    const float* __restrict__ bias, float* __restrict__ C,
    __half* __restrict__ OutF,
    int Md, int Nd, int Kd)
{
    extern __shared__ __align__(1024) unsigned char smem[];
    const int tid = threadIdx.x;
    const int wid = tid >> 5;
    const int lane = tid & 31;
    const int wm = wid >> 2;              // 0..1
    const int wn = wid & 3;               // 0..3
    const int bm = blockIdx.y * 128;
    const int bn = blockIdx.x * 256;
    const uint32_t sbase = smem_u32(smem);
    const int nchunk = Kd >> 5;           // 64
    const bool twopass = (Al != nullptr);

#define LOAD_STAGE(stage, k0)                                                   \
    {                                                                            \
        uint32_t sb = sbase + (stage) * GSTAGE;                                  \
        _Pragma("unroll")                                                        \
        for (int j = 0; j < 2; j++) {                                            \
            int idx = tid + j * 256;                                             \
            int r = idx >> 2, c = idx & 3;                                       \
            uint32_t so = swz((uint32_t)(r * 64 + c * 16));                      \
            size_t ga = (size_t)(bm + r) * Kd + (k0) + c * 8;                    \
            cpa16(sb + so, Ah + ga);                                             \
            if (twopass) cpa16(sb + 8192 + so, Al + ga);                         \
        }                                                                        \
        _Pragma("unroll")                                                        \
        for (int j = 0; j < 4; j++) {                                            \
            int idx = tid + j * 256;                                             \
            int r = idx >> 2, c = idx & 3;                                       \
            uint32_t so = swz((uint32_t)(r * 64 + c * 16));                      \
            size_t gb = (size_t)(bn + r) * Kd + (k0) + c * 8;                    \
            cpa16(sb + 16384 + so, Bf + gb);                                     \
        }                                                                        \
        asm volatile("cp.async.commit_group;" ::: "memory");                     \
    }

    LOAD_STAGE(0, 0)
    LOAD_STAGE(1, 32)

    float acc[4][8][4];
#pragma unroll
    for (int i = 0; i < 4; i++)
#pragma unroll
        for (int j = 0; j < 8; j++)
#pragma unroll
            for (int l = 0; l < 4; l++) acc[i][j][l] = 0.f;

    const int arow = lane & 15;
    const int akh = lane >> 4;
    const int brow8 = lane & 7;
    const int bkh = (lane >> 3) & 1;
    const int bni8 = (lane >> 4) & 1;

    for (int i = 0; i < nchunk; i++) {
        if (i + 2 < nchunk) {
            LOAD_STAGE((i + 2) % 3, (i + 2) * 32)
            asm volatile("cp.async.wait_group 2;" ::: "memory");
        } else if (i + 1 < nchunk) {
            asm volatile("cp.async.wait_group 1;" ::: "memory");
        } else {
            asm volatile("cp.async.wait_group 0;" ::: "memory");
        }
        __syncthreads();

        const uint32_t sb = sbase + (i % 3) * GSTAGE;
#pragma unroll
        for (int ks = 0; ks < 2; ks++) {
            uint32_t ah[4][4], al[4][4], bf[4][4];
#pragma unroll
            for (int mi = 0; mi < 4; mi++) {
                uint32_t off = swz((uint32_t)((wm * 64 + mi * 16 + arow) * 64 + ks * 32 + akh * 16));
                ldx4(ah[mi], sb + off);
                if (twopass) ldx4(al[mi], sb + 8192 + off);
            }
#pragma unroll
            for (int nj = 0; nj < 4; nj++) {
                int r = wn * 64 + nj * 16 + bni8 * 8 + brow8;
                uint32_t off = swz((uint32_t)(r * 64 + ks * 32 + bkh * 16));
                ldx4(bf[nj], sb + 16384 + off);
            }
            // hi sweep
#pragma unroll
            for (int mi = 0; mi < 4; mi++)
#pragma unroll
                for (int nj = 0; nj < 4; nj++) {
                    mma_f16(acc[mi][2 * nj],     ah[mi], &bf[nj][0]);
                    mma_f16(acc[mi][2 * nj + 1], ah[mi], &bf[nj][2]);
                }
            // lo sweep (2-pass only)
            if (twopass) {
#pragma unroll
                for (int mi = 0; mi < 4; mi++)
#pragma unroll
                    for (int nj = 0; nj < 4; nj++) {
                        mma_f16(acc[mi][2 * nj],     al[mi], &bf[nj][0]);
                        mma_f16(acc[mi][2 * nj + 1], al[mi], &bf[nj][2]);
                    }
            }
        }
        __syncthreads();
    }

    // Epilogue
#pragma unroll
    for (int mi = 0; mi < 4; mi++) {
        int r0 = bm + wm * 64 + mi * 16 + (lane >> 2);
#pragma unroll
        for (int ni = 0; ni < 8; ni++) {
            int col = bn + wn * 64 + ni * 8 + (lane & 3) * 2;
            float b0 = bias[col], b1 = bias[col + 1];
            float x0 = acc[mi][ni][0] + b0, x1 = acc[mi][ni][1] + b1;
            float x2 = acc[mi][ni][2] + b0, x3 = acc[mi][ni][3] + b1;
            if (C) {
                *(float2*)(C + (size_t)r0 * Nd + col) = make_float2(x0, x1);
                *(float2*)(C + (size_t)(r0 + 8) * Nd + col) = make_float2(x2, x3);
            }
            if (OutF) {
                *(__half2*)(OutF + (size_t)r0 * Nd + col) = __floats2half2_rn(x0, x1);
                *(__half2*)(OutF + (size_t)(r0 + 8) * Nd + col) = __floats2half2_rn(x2, x3);
            }
        }
    }
#undef LOAD_STAGE
}

// ---------------------------------------------------------------------------
// fp32 -> fp16 hi/lo split (lo optional)
// ---------------------------------------------------------------------------
__global__ __launch_bounds__(256) void split_f16(
    const float4* __restrict__ src, __half2* __restrict__ hi,
    __half2* __restrict__ lo, int n4)
{
    int i = blockIdx.x * 256 + threadIdx.x;
    if (i >= n4) return;
    float4 v = src[i];
    __half2 l0, l1;
    __half2 h0 = split_h2(v.x, v.y, l0);
    __half2 h1 = split_h2(v.z, v.w, l1);
    hi[2 * i] = h0; hi[2 * i + 1] = h1;
    if (lo) { lo[2 * i] = l0; lo[2 * i + 1] = l1; }
}

// ---------------------------------------------------------------------------
// Fused RMSNorm + interleaved RoPE -> fp16 hi (+ optional lo split).
// ---------------------------------------------------------------------------
__global__ __launch_bounds__(256) void rmsnorm_rope_f16(
    const float* __restrict__ h, const float* __restrict__ w,
    const float* __restrict__ cosb, const float* __restrict__ sinb,
    __half* __restrict__ outh, __half* __restrict__ outl)
{
    const int row = blockIdx.x;
    const int t = row & (T_ - 1);
    const float* hr = h + (size_t)row * D_;

    float ss = 0.f;
    for (int i = threadIdx.x; i < D_; i += 256) { float v = hr[i]; ss += v * v; }
#pragma unroll
    for (int o = 16; o > 0; o >>= 1) ss += __shfl_xor_sync(0xffffffffu, ss, o);
    __shared__ float red[8];
    __shared__ float s_inv;
    if ((threadIdx.x & 31) == 0) red[threadIdx.x >> 5] = ss;
    __syncthreads();
    if (threadIdx.x == 0) {
        float s = 0.f;
        for (int i = 0; i < 8; i++) s += red[i];
        s_inv = rsqrtf(s * (1.0f / D_) + 1e-6f);
    }
    __syncthreads();
    const float inv = s_inv;
    const float* ct = cosb + (size_t)t * D_;
    const float* st = sinb + (size_t)t * D_;
    __half2* oh2 = (__half2*)(outh + (size_t)row * D_);
    __half2* ol2 = outl ? (__half2*)(outl + (size_t)row * D_) : nullptr;
    for (int i = threadIdx.x; i < D_ / 2; i += 256) {
        int i2 = i * 2;
        float e = hr[i2] * inv * w[i2];
        float o = hr[i2 + 1] * inv * w[i2 + 1];
        float v0 = e * ct[i2]     - o * st[i2];
        float v1 = o * ct[i2 + 1] + e * st[i2 + 1];
        __half2 lo;
        __half2 hi = split_h2(v0, v1, lo);
        oh2[i] = hi;
        if (ol2) ol2[i] = lo;
    }
}

// ---------------------------------------------------------------------------
// fp16 2-pass mma.sync flash attention (non-causal); output fp16 hi/lo split.
// Q split, K single, V single (P split in-register).
// ---------------------------------------------------------------------------
#define FA_STAGE 32768

__global__ __launch_bounds__(128, 1) void flash_attn_f16(
    const __half* __restrict__ Qh, const __half* __restrict__ Ql,
    const __half* __restrict__ Kf, const __half* __restrict__ Vf,
    __half* __restrict__ Oh, __half* __restrict__ Ol)
{
    extern __shared__ __align__(1024) unsigned char smem[];
    const int tid = threadIdx.x;
    const int wid = tid >> 5, lane = tid & 31;
    const int b = blockIdx.z, h = blockIdx.y;
    const int q0 = blockIdx.x * 64;
    const uint32_t sbase = smem_u32(smem);
    const size_t rowbase = ((size_t)b * T_) * D_ + h * DH_;

#define LOADKV(it_, stg)                                                         \
    {                                                                            \
        uint32_t sb_ = sbase + (stg) * FA_STAGE;                                 \
        size_t base_ = rowbase + (size_t)((it_) * 64) * D_;                      \
        for (int t = tid; t < 1024; t += 128) {                                  \
            int r_ = t >> 4, c_ = t & 15;                                        \
            uint32_t ph_ = r_ * 256 + ((c_ ^ (r_ & 7)) << 4);                    \
            size_t g_ = base_ + (size_t)r_ * D_ + c_ * 8;                        \
            cpa16(sb_ + ph_,          Kf + g_);                                  \
            cpa16(sb_ + 16384 + ph_,  Vf + g_);                                  \
        }                                                                        \
        asm volatile("cp.async.commit_group;" ::: "memory");                     \
    }

    // stage Q (hi at 0, lo at +16K), build fragments
    for (int t = tid; t < 1024; t += 128) {
        int r = t >> 4, c = t & 15;
        uint32_t ph = r * 256 + ((c ^ (r & 7)) << 4);
        size_t g = rowbase + (size_t)(q0 + r) * D_ + c * 8;
        cpa16(sbase + ph, Qh + g);
        cpa16(sbase + 16384 + ph, Ql + g);
    }
    asm volatile("cp.async.commit_group;" ::: "memory");
    asm volatile("cp.async.wait_group 0;" ::: "memory");
    __syncthreads();

    uint32_t qh[8][4], ql[8][4];
    {
        int r = wid * 16 + (lane & 15);
        int khalf = lane >> 4;
#pragma unroll
        for (int kk = 0; kk < 8; kk++) {
            int chunk = kk * 2 + khalf;
            uint32_t ph = r * 256 + ((chunk ^ (r & 7)) << 4);
            ldx4(qh[kk], sbase + ph);
            ldx4(ql[kk], sbase + 16384 + ph);
        }
    }
    __syncthreads();

    float o[16][4];
#pragma unroll
    for (int i = 0; i < 16; i++)
#pragma unroll
        for (int j = 0; j < 4; j++) o[i][j] = 0.f;
    float m0 = -1e30f, m1 = -1e30f, l0 = 0.f, l1 = 0.f;

    LOADKV(0, 0)
    LOADKV(1, 1)

    const float scale = 0.08838834764831845f;
    const int NIT = T_ / 64;

    for (int it = 0; it < NIT; it++) {
        if (it < NIT - 1) { asm volatile("cp.async.wait_group 1;" ::: "memory"); }
        else              { asm volatile("cp.async.wait_group 0;" ::: "memory"); }
        __syncthreads();
        const uint32_t sb = sbase + (it & 1) * FA_STAGE;

        // ---- S = (Qh+Ql) K^T ----
        float s[8][4];
#pragma unroll
        for (int n = 0; n < 8; n++)
#pragma unroll
            for (int j = 0; j < 4; j++) s[n][j] = 0.f;

        const int krow_lo = lane & 7;
        const int kkh = ((lane & 15) >> 3) & 1;
#pragma unroll
        for (int kk = 0; kk < 8; kk++) {
            uint32_t bhv[8][2];
#pragma unroll
            for (int n = 0; n < 8; n++) {
                int r = n * 8 + krow_lo;
                int chunk = kk * 2 + kkh;
                uint32_t ph = r * 256 + ((chunk ^ (r & 7)) << 4);
                ldx2(bhv[n], sb + ph);
            }
#pragma unroll
            for (int n = 0; n < 8; n++) mma_f16(s[n], qh[kk], bhv[n]);
#pragma unroll
            for (int n = 0; n < 8; n++) mma_f16(s[n], ql[kk], bhv[n]);
        }

#pragma unroll
        for (int n = 0; n < 8; n++)
#pragma unroll
            for (int j = 0; j < 4; j++) s[n][j] *= scale;

        // ---- online softmax ----
        float cm0 = -1e30f, cm1 = -1e30f;
#pragma unroll
        for (int n = 0; n < 8; n++) {
            cm0 = fmaxf(cm0, fmaxf(s[n][0], s[n][1]));
            cm1 = fmaxf(cm1, fmaxf(s[n][2], s[n][3]));
        }
        cm0 = fmaxf(cm0, __shfl_xor_sync(0xffffffffu, cm0, 1));
        cm0 = fmaxf(cm0, __shfl_xor_sync(0xffffffffu, cm0, 2));
        cm1 = fmaxf(cm1, __shfl_xor_sync(0xffffffffu, cm1, 1));
        cm1 = fmaxf(cm1, __shfl_xor_sync(0xffffffffu, cm1, 2));
        float mn0 = fmaxf(m0, cm0), mn1 = fmaxf(m1, cm1);
        float a0 = __expf(m0 - mn0), a1 = __expf(m1 - mn1);
        float sum0 = 0.f, sum1 = 0.f;
#pragma unroll
        for (int n = 0; n < 8; n++) {
            s[n][0] = __expf(s[n][0] - mn0);
            s[n][1] = __expf(s[n][1] - mn0);
            s[n][2] = __expf(s[n][2] - mn1);
            s[n][3] = __expf(s[n][3] - mn1);
            sum0 += s[n][0] + s[n][1];
            sum1 += s[n][2] + s[n][3];
        }
        sum0 += __shfl_xor_sync(0xffffffffu, sum0, 1);
        sum0 += __shfl_xor_sync(0xffffffffu, sum0, 2);
        sum1 += __shfl_xor_sync(0xffffffffu, sum1, 1);
        sum1 += __shfl_xor_sync(0xffffffffu, sum1, 2);
        l0 = l0 * a0 + sum0;
        l1 = l1 * a1 + sum1;
        m0 = mn0; m1 = mn1;
#pragma unroll
        for (int ni = 0; ni < 16; ni++) {
            o[ni][0] *= a0; o[ni][1] *= a0;
            o[ni][2] *= a1; o[ni][3] *= a1;
        }

        // ---- O += (Ph+Pl) V ----
        const int vrow = lane & 15;
#pragma unroll
        for (int j = 0; j < 4; j++) {
            uint32_t pa[4], pb[4];
#pragma unroll
            for (int half = 0; half < 2; half++) {
                float x0 = s[2 * j + half][0], x1 = s[2 * j + half][1];
                float x2 = s[2 * j + half][2], x3 = s[2 * j + half][3];
                __half h0 = __float2half_rn(x0), h1 = __float2half_rn(x1);
                __half h2 = __float2half_rn(x2), h3 = __float2half_rn(x3);
                pa[2 * half]     = pkh(h0, h1);
                pa[2 * half + 1] = pkh(h2, h3);
                pb[2 * half]     = pkh(__float2half_rn(x0 - __half2float(h0)),
                                       __float2half_rn(x1 - __half2float(h1)));
                pb[2 * half + 1] = pkh(__float2half_rn(x2 - __half2float(h2)),
                                       __float2half_rn(x3 - __half2float(h3)));
            }
            int r = j * 16 + vrow;
#pragma unroll
            for (int blk = 0; blk < 2; blk++) {
                uint32_t vhv[8][2];
#pragma unroll
                for (int nn = 0; nn < 8; nn++) {
                    int ni = blk * 8 + nn;
                    uint32_t ph = r * 256 + ((ni ^ (r & 7)) << 4);
                    ldx2t(vhv[nn], sb + 16384 + ph);
                }
#pragma unroll
                for (int nn = 0; nn < 8; nn++) mma_f16(o[blk * 8 + nn], pa, vhv[nn]);
#pragma unroll
                for (int nn = 0; nn < 8; nn++) mma_f16(o[blk * 8 + nn], pb, vhv[nn]);
            }
        }
        __syncthreads();
        if (it + 2 < NIT) { LOADKV(it + 2, it & 1) }
    }

    // ---- store as fp16 hi/lo split ----
    float i0 = 1.f / l0, i1 = 1.f / l1;
    int r_lo = q0 + wid * 16 + (lane >> 2);
#pragma unroll
    for (int ni = 0; ni < 16; ni++) {
        int col = ni * 8 + (lane & 3) * 2;
        size_t idx0 = rowbase + (size_t)r_lo * D_ + col;
        size_t idx1 = rowbase + (size_t)(r_lo + 8) * D_ + col;
        __half2 lo0, lo1;
        __half2 h0 = split_h2(o[ni][0] * i0, o[ni][1] * i0, lo0);
        __half2 h1 = split_h2(o[ni][2] * i1, o[ni][3] * i1, lo1);
        *(__half2*)(Oh + idx0) = h0;
        *(__half2*)(Ol + idx0) = lo0;
        *(__half2*)(Oh + idx1) = h1;
        *(__half2*)(Ol + idx1) = lo1;
    }
#undef LOADKV
}

// ---------------------------------------------------------------------------
// Launch
// ---------------------------------------------------------------------------
extern "C" void kernel_launch(void* const* d_in, const int* in_sizes, int n_in,
                              void* d_out, int out_size)
{
    const float* x    = (const float*)d_in[0];
    const float* cosb = (const float*)d_in[1];
    const float* sinb = (const float*)d_in[2];
    const float* Wq   = (const float*)d_in[3];
    const float* bq   = (const float*)d_in[4];
    const float* Wk   = (const float*)d_in[5];
    const float* bk   = (const float*)d_in[6];
    const float* Wv   = (const float*)d_in[7];
    const float* bv   = (const float*)d_in[8];
    const float* qnw  = (const float*)d_in[9];
    const float* knw  = (const float*)d_in[10];
    const float* Wo   = (const float*)d_in[11];
    const float* bo   = (const float*)d_in[12];
    float* out = (float*)d_out;

    float *qp, *kp;
    cudaGetSymbolAddress((void**)&qp, g_q);
    cudaGetSymbolAddress((void**)&kp, g_k);
    __half *xh, *qhp, *qlp, *k16, *v16, *ohp, *olp;
    __half *wq16, *wk16, *wv16, *wo16;
    cudaGetSymbolAddress((void**)&xh, g_xh);
    cudaGetSymbolAddress((void**)&qhp, g_qh);   cudaGetSymbolAddress((void**)&qlp, g_ql);
    cudaGetSymbolAddress((void**)&k16, g_k16);  cudaGetSymbolAddress((void**)&v16, g_v16);
    cudaGetSymbolAddress((void**)&ohp, g_oh);   cudaGetSymbolAddress((void**)&olp, g_ol);
    cudaGetSymbolAddress((void**)&wq16, g_wq16); cudaGetSymbolAddress((void**)&wk16, g_wk16);
    cudaGetSymbolAddress((void**)&wv16, g_wv16); cudaGetSymbolAddress((void**)&wo16, g_wo16);

    const int nx4 = M_ * D_ / 4;
    const int nw4 = D_ * D_ / 4;
    split_f16<<<nx4 / 256, 256>>>((const float4*)x,  (__half2*)xh,   nullptr, nx4);
    split_f16<<<nw4 / 256, 256>>>((const float4*)Wq, (__half2*)wq16, nullptr, nw4);
    split_f16<<<nw4 / 256, 256>>>((const float4*)Wk, (__half2*)wk16, nullptr, nw4);
    split_f16<<<nw4 / 256, 256>>>((const float4*)Wv, (__half2*)wv16, nullptr, nw4);
    split_f16<<<nw4 / 256, 256>>>((const float4*)Wo, (__half2*)wo16, nullptr, nw4);

    cudaFuncSetAttribute(gemm_f16_2p, cudaFuncAttributeMaxDynamicSharedMemorySize, GEMM_SMEM);
    dim3 ggrid(D_ / 256, M_ / 128);   // (8, 32)
    // QKV projections: single-pass fp16 (x rounded; error budget reallocation)
    gemm_f16_2p<<<ggrid, 256, GEMM_SMEM>>>(xh, nullptr, wq16, bq, qp, nullptr, M_, D_, D_);
    gemm_f16_2p<<<ggrid, 256, GEMM_SMEM>>>(xh, nullptr, wk16, bk, kp, nullptr, M_, D_, D_);
    gemm_f16_2p<<<ggrid, 256, GEMM_SMEM>>>(xh, nullptr, wv16, bv, nullptr, v16, M_, D_, D_);

    rmsnorm_rope_f16<<<M_, 256>>>(qp, qnw, cosb, sinb, qhp, qlp);
    rmsnorm_rope_f16<<<M_, 256>>>(kp, knw, cosb, sinb, k16, nullptr);

    cudaFuncSetAttribute(flash_attn_f16, cudaFuncAttributeMaxDynamicSharedMemorySize, 2 * FA_STAGE);
    flash_attn_f16<<<dim3(T_ / 64, H_, B_), 128, 2 * FA_STAGE>>>(qhp, qlp, k16, v16, ohp, olp);

    // O-projection: keep 2-pass (final output accuracy)
    gemm_f16_2p<<<ggrid, 256, GEMM_SMEM>>>(ohp, olp, wo16, bo, out, nullptr, M_, D_, D_);
}